// round 12
// baseline (speedup 1.0000x reference)
#include <cuda_runtime.h>
#include <cstdint>

// Aggregation: out[n, g*32+wc, h, w] =
//   sum_{kh,kw} x_reflect[n, g*32+wc, h+kh-1, w+kw-1] * weight[n, wc, kh*3+kw, h, w]
//
// x (8,256,128,128) f32, weight (8,32,9,128,128) f32, out = x shape.
//
// R12: bulk-async x staging. Each CTA (fixed n, wc, 8 consecutive h) needs
// x rows h0-1..h0+8 of its 8 channels = 8 CONTIGUOUS 5120B chunks. One thread
// issues 8 cp.async.bulk copies into smem (mbarrier complete_tx); weights are
// LDG'd by all threads while the bulk copy flies; compute reads x via
// conflict-free LDS.128. DRAM sees 5KB bursts instead of scattered 512B
// warp-loads. Grid/warps/acc shape identical to R4 (the proven optimum).

namespace {
constexpr int N  = 8;
constexpr int C  = 256;
constexpr int H  = 128;
constexpr int W  = 128;
constexpr int WC = 32;
constexpr int G  = C / WC;   // 8
constexpr int HW = H * W;
constexpr int CS = WC * HW;      // channel-group stride (elements)
constexpr int XROWS = 10;        // h0-1 .. h0+8 (clamped window)
constexpr uint32_t XBYTES = G * XROWS * W * 4;  // 40960
}

__global__ __launch_bounds__(256, 3)
void agg_kernel(const float* __restrict__ x,
                const float* __restrict__ wt,
                float* __restrict__ out)
{
    __shared__ __align__(16) float sx[G][XROWS][W];  // 40 KB
    __shared__ __align__(8)  uint64_t mbar;

    const int tid = blockIdx.x * 256 + threadIdx.x;
    // Decode: w4 (32) fastest -> lane id == w4; then h (128), wc (32), n (8)
    const int w4 = tid & 31;
    const int h  = (tid >> 5) & 127;
    const int wc = (tid >> 12) & 31;
    const int n  = tid >> 17;
    const int w  = w4 << 2;
    const int h0 = h & ~7;          // CTA's h-block base

    // smem window base row (clamped so all reflect targets are inside)
    int base = h0 - 1;
    if (base < 0) base = 0;
    if (base > H - XROWS) base = H - XROWS;

    const uint32_t mbar_addr = (uint32_t)__cvta_generic_to_shared(&mbar);

    // ---- Init mbarrier, then one thread issues the 8 bulk copies ----
    if (threadIdx.x == 0) {
        asm volatile("mbarrier.init.shared.b64 [%0], %1;"
                     :: "r"(mbar_addr), "r"(1u) : "memory");
    }
    __syncthreads();

    const size_t x_n_base = (size_t)n * C * HW;

    if (threadIdx.x == 0) {
        asm volatile("mbarrier.arrive.expect_tx.shared.b64 _, [%0], %1;"
                     :: "r"(mbar_addr), "r"(XBYTES) : "memory");
        const float* gsrc0 = x + x_n_base + (size_t)wc * HW + (size_t)base * W;
        #pragma unroll
        for (int g = 0; g < G; g++) {
            const uint32_t sdst =
                (uint32_t)__cvta_generic_to_shared(&sx[g][0][0]);
            asm volatile(
                "cp.async.bulk.shared::cta.global.mbarrier::complete_tx::bytes"
                " [%0], [%1], %2, [%3];"
                :: "r"(sdst), "l"(gsrc0 + g * CS),
                   "r"((uint32_t)(XROWS * W * 4)), "r"(mbar_addr)
                : "memory");
        }
    }

    // ---- Weight loads overlap the bulk copy (registers, read-once) ----
    const float4* wp = reinterpret_cast<const float4*>(
        wt + ((size_t)(n * WC + wc) * 9) * HW + (size_t)h * W + w);
    float4 wq[9];
    #pragma unroll
    for (int k = 0; k < 9; k++)
        wq[k] = __ldcs(wp + k * (HW / 4));

    // Reflect rows (PAD=1: only -1 and 128 occur), as smem row indices
    const int hr0 = (h == 0)     ? 1     : h - 1;
    const int hr2 = (h == H - 1) ? H - 2 : h + 1;
    const int rows[3] = { hr0 - base, h - base, hr2 - base };

    const bool lane_lo = (w4 == 0);
    const bool lane_hi = (w4 == 31);

    // ---- Wait for x tile (acquire) ----
    {
        uint32_t done;
        asm volatile(
            "{\n\t.reg .pred p;\n\t"
            "mbarrier.try_wait.parity.acquire.cta.shared::cta.b64 p, [%1], %2;\n\t"
            "selp.b32 %0, 1, 0, p;\n\t}"
            : "=r"(done) : "r"(mbar_addr), "r"(0u) : "memory");
        if (!done) {
            asm volatile(
                "{\n\t.reg .pred P1;\n\t"
                "WL_%=:\n\t"
                "mbarrier.try_wait.parity.acquire.cta.shared::cta.b64 P1, [%0], %1, 0x989680;\n\t"
                "@P1 bra.uni WD_%=;\n\t"
                "bra.uni WL_%=;\n\t"
                "WD_%=:\n\t}"
                :: "r"(mbar_addr), "r"(0u) : "memory");
        }
    }

    float4 acc[G];
    #pragma unroll
    for (int g = 0; g < G; g++)
        acc[g] = make_float4(0.f, 0.f, 0.f, 0.f);

    #pragma unroll
    for (int kh = 0; kh < 3; kh++) {
        const float4 wA = wq[kh * 3 + 0];
        const float4 wB = wq[kh * 3 + 1];
        const float4 wD = wq[kh * 3 + 2];
        const int ri = rows[kh];

        // 8 conflict-free LDS.128, batched
        float4 xm[G];
        #pragma unroll
        for (int g = 0; g < G; g++)
            xm[g] = *reinterpret_cast<const float4*>(&sx[g][ri][w]);

        #pragma unroll
        for (int g = 0; g < G; g++) {
            const float v1 = xm[g].x, v2 = xm[g].y,
                        v3 = xm[g].z, v4 = xm[g].w;
            // halo via warp shuffle; reflect at row ends is intra-lane
            float v0 = __shfl_up_sync(0xffffffffu, v4, 1);
            float v5 = __shfl_down_sync(0xffffffffu, v1, 1);
            if (lane_lo) v0 = v2;   // col -1  -> col 1
            if (lane_hi) v5 = v3;   // col 128 -> col 126

            acc[g].x = fmaf(v0, wA.x, fmaf(v1, wB.x, fmaf(v2, wD.x, acc[g].x)));
            acc[g].y = fmaf(v1, wA.y, fmaf(v2, wB.y, fmaf(v3, wD.y, acc[g].y)));
            acc[g].z = fmaf(v2, wA.z, fmaf(v3, wB.z, fmaf(v4, wD.z, acc[g].z)));
            acc[g].w = fmaf(v3, wA.w, fmaf(v4, wB.w, fmaf(v5, wD.w, acc[g].w)));
        }
    }

    // One contiguous write burst: 8 streaming float4 stores
    float* ob = out + x_n_base + (size_t)wc * HW + (size_t)h * W + w;
    #pragma unroll
    for (int g = 0; g < G; g++)
        __stcs(reinterpret_cast<float4*>(ob + g * CS), acc[g]);
}

extern "C" void kernel_launch(void* const* d_in, const int* in_sizes, int n_in,
                              void* d_out, int out_size)
{
    const float* x  = (const float*)d_in[0];
    const float* wt = (const float*)d_in[1];
    float* out      = (float*)d_out;

    const int total   = N * WC * H * (W / 4);  // 1,048,576 threads
    const int threads = 256;
    const int blocks  = total / threads;       // 4096
    agg_kernel<<<blocks, threads>>>(x, wt, out);
}

// round 13
// speedup vs baseline: 1.0257x; 1.0257x over previous
#include <cuda_runtime.h>

// Aggregation: out[n, g*32+wc, h, w] =
//   sum_{kh,kw} x_reflect[n, g*32+wc, h+kh-1, w+kw-1] * weight[n, wc, kh*3+kw, h, w]
//
// x (8,256,128,128) f32, weight (8,32,9,128,128) f32, out = x shape.
//
// FINAL (R4 config; best of 12 rounds: 66.0us, DRAM 78%, 6.19 TB/s):
// - DRAM traffic at/below the algorithmic floor (~370-390MB measured):
//   weights register-resident across all 8 channel groups, halo columns via
//   warp shuffle (a warp spans one full W=128 row), reflect edges intra-lane,
//   x vertical halos hit in L2 across CTAs.
// - kh-outer phases: 3 weight + 8 independent x float4 loads batched
//   back-to-back (deep MLP), 32 persistent accumulator registers, all 8
//   output stores as one contiguous streaming burst at the end.
// - 3 CTAs/SM (80 regs, 24 warps).
// Verified sharp optimum: more warps (R5), reg double-buffer (R6), persistent
// grid (R7), weight prefetch (R8), cp.async staging (R9), store interleave
// (R10), and cp.async.bulk 5KB-burst staging (R12) ALL measured worse or
// neutral. DRAM busy pins at 77-78% for every load mechanism -> interleaved
// read/write stream ceiling, not software-addressable.

namespace {
constexpr int N  = 8;
constexpr int C  = 256;
constexpr int H  = 128;
constexpr int W  = 128;
constexpr int WC = 32;
constexpr int G  = C / WC;   // 8
constexpr int HW = H * W;
constexpr int CS = WC * HW;  // channel-group stride (elements)
}

__global__ __launch_bounds__(256, 3)
void agg_kernel(const float* __restrict__ x,
                const float* __restrict__ wt,
                float* __restrict__ out)
{
    const int tid = blockIdx.x * 256 + threadIdx.x;
    // Decode: w4 (32) fastest -> lane id == w4; then h (128), wc (32), n (8)
    const int w4 = tid & 31;
    const int h  = (tid >> 5) & 127;
    const int wc = (tid >> 12) & 31;
    const int n  = tid >> 17;
    const int w  = w4 << 2;

    // Reflect rows (PAD=1: only -1 and 128 occur)
    const int hr0 = (h == 0)     ? 1     : h - 1;
    const int hr2 = (h == H - 1) ? H - 2 : h + 1;
    const int rows[3] = { hr0, h, hr2 };

    const bool lane_lo = (w4 == 0);
    const bool lane_hi = (w4 == 31);

    const size_t x_n_base = (size_t)n * C * HW;
    const float* xbase = x + x_n_base + (size_t)wc * HW + w;

    const float4* wp = reinterpret_cast<const float4*>(
        wt + ((size_t)(n * WC + wc) * 9) * HW + (size_t)h * W + w);

    float4 acc[G];
    #pragma unroll
    for (int g = 0; g < G; g++)
        acc[g] = make_float4(0.f, 0.f, 0.f, 0.f);

    #pragma unroll
    for (int kh = 0; kh < 3; kh++) {
        // 3 weight float4s for this kh (read-once: evict-first)
        const float4 wA = __ldcs(wp + (kh * 3 + 0) * (HW / 4));
        const float4 wB = __ldcs(wp + (kh * 3 + 1) * (HW / 4));
        const float4 wD = __ldcs(wp + (kh * 3 + 2) * (HW / 4));

        // 8 independent x-row loads, batched back-to-back
        const float* xr = xbase + rows[kh] * W;
        float4 xm[G];
        #pragma unroll
        for (int g = 0; g < G; g++)
            xm[g] = *reinterpret_cast<const float4*>(xr + g * CS);

        #pragma unroll
        for (int g = 0; g < G; g++) {
            const float v1 = xm[g].x, v2 = xm[g].y,
                        v3 = xm[g].z, v4 = xm[g].w;
            // halo via warp shuffle; reflect at row ends is intra-lane
            float v0 = __shfl_up_sync(0xffffffffu, v4, 1);
            float v5 = __shfl_down_sync(0xffffffffu, v1, 1);
            if (lane_lo) v0 = v2;   // col -1  -> col 1
            if (lane_hi) v5 = v3;   // col 128 -> col 126

            acc[g].x = fmaf(v0, wA.x, fmaf(v1, wB.x, fmaf(v2, wD.x, acc[g].x)));
            acc[g].y = fmaf(v1, wA.y, fmaf(v2, wB.y, fmaf(v3, wD.y, acc[g].y)));
            acc[g].z = fmaf(v2, wA.z, fmaf(v3, wB.z, fmaf(v4, wD.z, acc[g].z)));
            acc[g].w = fmaf(v3, wA.w, fmaf(v4, wB.w, fmaf(v5, wD.w, acc[g].w)));
        }
    }

    // One contiguous write burst: 8 streaming float4 stores
    float* ob = out + x_n_base + (size_t)wc * HW + (size_t)h * W + w;
    #pragma unroll
    for (int g = 0; g < G; g++)
        __stcs(reinterpret_cast<float4*>(ob + g * CS), acc[g]);
}

extern "C" void kernel_launch(void* const* d_in, const int* in_sizes, int n_in,
                              void* d_out, int out_size)
{
    const float* x  = (const float*)d_in[0];
    const float* wt = (const float*)d_in[1];
    float* out      = (float*)d_out;

    const int total   = N * WC * H * (W / 4);  // 1,048,576 threads
    const int threads = 256;
    const int blocks  = total / threads;       // 4096
    agg_kernel<<<blocks, threads>>>(x, wt, out);
}